// round 1
// baseline (speedup 1.0000x reference)
#include <cuda_runtime.h>
#include <cstdint>

// Problem constants: input (64, 65536, 6) f32, output (64, 640) f32.
#define BATCHES     64
#define POINTS      65536
#define PAIRS       (POINTS / 2)            // 32768 pairs of points per batch
#define F4_PER_B    (POINTS * 6 / 4)        // 98304 float4 per batch
#define NUM_BINS    4
#define NUM_CELLS   64
#define STATS       10                      // count, sum_pic(3), sum_cov(6)
#define FEAT        (NUM_CELLS * STATS)     // 640

// Kernel 1 (bbox) config
#define BPB1        32                      // blocks per batch
#define T1          256
#define PAIRS_PER_BLK1 (PAIRS / BPB1)       // 1024
#define ITER1       (PAIRS_PER_BLK1 / T1)   // 4

// Kernel 2 (accumulate) config
#define BPB2        16
#define T2          256
#define PAIRS_PER_BLK2 (PAIRS / BPB2)       // 2048
#define ITER2       (PAIRS_PER_BLK2 / T2)   // 8
#define REPL        16                      // smem histogram replicas
#define HSTRIDE     641                     // 640 + 1 pad -> bank spread (641 % 32 == 1)

// Device scratch (no cudaMalloc allowed)
__device__ unsigned int g_bbox[BATCHES];
__device__ float        g_sums[BATCHES * FEAT];

// ---------------------------------------------------------------------------
// Kernel 0: zero scratch
// ---------------------------------------------------------------------------
__global__ void k_init() {
    int b = blockIdx.x, t = threadIdx.x;
    if (t == 0) g_bbox[b] = 0u;
    for (int i = t; i < FEAT; i += blockDim.x) g_sums[b * FEAT + i] = 0.0f;
}

// ---------------------------------------------------------------------------
// Kernel 1: per-batch bbox_max = max(|pos|)
// Data layout per point pair (12 floats = 3 float4):
//   a = [p0x p0y p0z o0x]  b = [o0y o0z p1x p1y]  c = [p1z o1x o1y o1z]
// ---------------------------------------------------------------------------
__global__ __launch_bounds__(T1) void k_bbox(const float4* __restrict__ in4) {
    const int batch = blockIdx.y;
    const int tid = threadIdx.x;
    const float4* p = in4 + (size_t)batch * F4_PER_B;
    const int base = blockIdx.x * PAIRS_PER_BLK1;

    float m = 0.0f;
#pragma unroll
    for (int k = 0; k < ITER1; k++) {
        int j = base + tid + k * T1;
        float4 a = p[3 * j + 0];
        float4 b = p[3 * j + 1];
        float4 c = p[3 * j + 2];
        m = fmaxf(m, fmaxf(fmaxf(fabsf(a.x), fabsf(a.y)), fabsf(a.z)));
        m = fmaxf(m, fmaxf(fmaxf(fabsf(b.z), fabsf(b.w)), fabsf(c.x)));
    }
#pragma unroll
    for (int o = 16; o > 0; o >>= 1)
        m = fmaxf(m, __shfl_xor_sync(0xFFFFFFFFu, m, o));

    __shared__ float sm[T1 / 32];
    if ((tid & 31) == 0) sm[tid >> 5] = m;
    __syncthreads();
    if (tid == 0) {
        float mm = sm[0];
#pragma unroll
        for (int i = 1; i < T1 / 32; i++) mm = fmaxf(mm, sm[i]);
        // positive floats: uint compare == float compare
        atomicMax(&g_bbox[batch], __float_as_uint(mm));
    }
}

// ---------------------------------------------------------------------------
// Kernel 2: bin points, accumulate (count, sum_pic, sum_cov) per cell.
// 16-way replicated smem histogram (replica = lane&15) kills same-address
// contention from the ~8 hot central cells; stride 641 spreads banks.
// ---------------------------------------------------------------------------
__device__ __forceinline__ void accum_point(
    float* __restrict__ h,  // replica base
    float px, float py, float pz,
    float ox, float oy, float oz,
    float bbox, float inv)
{
    float picx = (px + bbox) * inv;
    float picy = (py + bbox) * inv;
    float picz = (pz + bbox) * inv;
    int ix = (int)(picx * 4.0f); ix = min(max(ix, 0), 3);
    int iy = (int)(picy * 4.0f); iy = min(max(iy, 0), 3);
    int iz = (int)(picz * 4.0f); iz = min(max(iz, 0), 3);
    int cell = (ix * NUM_BINS + iy) * NUM_BINS + iz;
    float* d = h + cell * STATS;
    atomicAdd(d + 0, 1.0f);
    atomicAdd(d + 1, picx);
    atomicAdd(d + 2, picy);
    atomicAdd(d + 3, picz);
    atomicAdd(d + 4, ox * ox);
    atomicAdd(d + 5, ox * oy);
    atomicAdd(d + 6, ox * oz);
    atomicAdd(d + 7, oy * oy);
    atomicAdd(d + 8, oy * oz);
    atomicAdd(d + 9, oz * oz);
}

__global__ __launch_bounds__(T2) void k_accum(const float4* __restrict__ in4) {
    __shared__ float hist[REPL * HSTRIDE];   // 41 KB
    const int batch = blockIdx.y;
    const int tid = threadIdx.x;

    for (int i = tid; i < REPL * HSTRIDE; i += T2) hist[i] = 0.0f;
    __syncthreads();

    const float bbox = __uint_as_float(g_bbox[batch]);
    const float th = fmaxf(2.0f * bbox, 1e-5f);
    const float inv = 1.0f / th;

    const float4* p = in4 + (size_t)batch * F4_PER_B;
    const int base = blockIdx.x * PAIRS_PER_BLK2;
    float* hrep = hist + (tid & (REPL - 1)) * HSTRIDE;

#pragma unroll 2
    for (int k = 0; k < ITER2; k++) {
        int j = base + tid + k * T2;
        float4 a = p[3 * j + 0];
        float4 b = p[3 * j + 1];
        float4 c = p[3 * j + 2];
        accum_point(hrep, a.x, a.y, a.z, a.w, b.x, b.y, bbox, inv);
        accum_point(hrep, b.z, b.w, c.x, c.y, c.z, c.w, bbox, inv);
    }
    __syncthreads();

    // Reduce replicas and flush to global partials
    for (int w = tid; w < FEAT; w += T2) {
        float s = 0.0f;
#pragma unroll
        for (int r = 0; r < REPL; r++) s += hist[r * HSTRIDE + w];
        atomicAdd(&g_sums[batch * FEAT + w], s);
    }
}

// ---------------------------------------------------------------------------
// Kernel 3: finalize. One block per batch, 640 threads = one (cell, stat).
//   f_freq    = 0.001 * n * rsqrt(max(n,1))
//   f_mean[d] = (sum_pic[d] - n * grid[d]) * rsqrt(max(n,1))
//   f_cov     = sum_cov / max(n,1)
// then L2-normalize the 640-vector.
// ---------------------------------------------------------------------------
__global__ __launch_bounds__(FEAT) void k_final(float* __restrict__ out) {
    const int b = blockIdx.x;
    const int t = threadIdx.x;               // 0..639
    const int cell = t / STATS;
    const int s = t - cell * STATS;

    const float* sums = g_sums + b * FEAT;
    float cnt = sums[cell * STATS];
    float val = sums[t];
    float fc = fmaxf(cnt, 1.0f);
    float up = rsqrtf(fc);

    float f;
    if (s == 0) {
        f = 0.001f * cnt * up;
    } else if (s < 4) {
        int d = s - 1;
        int ci = (d == 0) ? (cell >> 4) : (d == 1) ? ((cell >> 2) & 3) : (cell & 3);
        float g = ((float)ci + 0.5f) * 0.25f;
        f = (val - cnt * g) * up;
    } else {
        f = val / fc;
    }

    // block-wide sum of f^2 over 640 threads (20 warps)
    float q = f * f;
#pragma unroll
    for (int o = 16; o > 0; o >>= 1)
        q += __shfl_xor_sync(0xFFFFFFFFu, q, o);

    __shared__ float wsum[FEAT / 32];
    __shared__ float s_inv;
    if ((t & 31) == 0) wsum[t >> 5] = q;
    __syncthreads();
    if (t == 0) {
        float ss = 0.0f;
#pragma unroll
        for (int i = 0; i < FEAT / 32; i++) ss += wsum[i];
        float n = sqrtf(ss);
        s_inv = 1.0f / fmaxf(n, 1e-12f);
    }
    __syncthreads();

    out[b * FEAT + t] = f * s_inv;
}

// ---------------------------------------------------------------------------
extern "C" void kernel_launch(void* const* d_in, const int* in_sizes, int n_in,
                              void* d_out, int out_size) {
    const float4* in4 = (const float4*)d_in[0];
    float* out = (float*)d_out;
    (void)in_sizes; (void)n_in; (void)out_size;

    k_init<<<BATCHES, 256>>>();
    k_bbox<<<dim3(BPB1, BATCHES), T1>>>(in4);
    k_accum<<<dim3(BPB2, BATCHES), T2>>>(in4);
    k_final<<<BATCHES, FEAT>>>(out);
}

// round 3
// speedup vs baseline: 2.1429x; 2.1429x over previous
#include <cuda_runtime.h>
#include <cstdint>

// Problem constants: input (64, 65536, 6) f32, output (64, 640) f32.
#define BATCHES     64
#define POINTS      65536
#define PAIRS       (POINTS / 2)            // 32768 pairs per batch
#define F4_PER_B    (POINTS * 6 / 4)        // 98304 float4 per batch
#define NUM_BINS    4
#define NUM_CELLS   64
#define STATS       10                      // count, sum_pic(3), sum_cov(6)
#define FEAT        (NUM_CELLS * STATS)     // 640

// Kernel 1 (bbox) config
#define BPB1        32
#define T1          256
#define PAIRS_PER_BLK1 (PAIRS / BPB1)       // 1024
#define ITER1       (PAIRS_PER_BLK1 / T1)   // 4

// Kernel 2 (accumulate) config
#define BPB2        4                       // 4 x 64 = 256 blocks (single wave @ 2/SM)
#define T2          512
#define PAIRS_PER_BLK2 (PAIRS / BPB2)       // 8192
#define ITER2       (PAIRS_PER_BLK2 / T2)   // 16
#define REPL        32                      // one replica per lane
#define HIST_WORDS  (FEAT * REPL)           // 20480 words = 80 KB
#define HIST_BYTES  (HIST_WORDS * 4)

// Device scratch (zero-initialized at module load; k_final restores zeros
// after each use so every graph replay sees the same initial state).
__device__ unsigned int g_bbox[BATCHES];
__device__ float        g_sums[BATCHES * FEAT];

// ---------------------------------------------------------------------------
// Kernel 1: per-batch bbox_max = max(|pos|)
// Layout per point pair (12 floats = 3 float4):
//   a = [p0x p0y p0z o0x]  b = [o0y o0z p1x p1y]  c = [p1z o1x o1y o1z]
// ---------------------------------------------------------------------------
__global__ __launch_bounds__(T1) void k_bbox(const float4* __restrict__ in4) {
    const int batch = blockIdx.y;
    const int tid = threadIdx.x;
    const float4* p = in4 + (size_t)batch * F4_PER_B;
    const int base = blockIdx.x * PAIRS_PER_BLK1;

    float m = 0.0f;
#pragma unroll
    for (int k = 0; k < ITER1; k++) {
        int j = base + tid + k * T1;
        float4 a = p[3 * j + 0];
        float4 b = p[3 * j + 1];
        float4 c = p[3 * j + 2];
        m = fmaxf(m, fmaxf(fmaxf(fabsf(a.x), fabsf(a.y)), fabsf(a.z)));
        m = fmaxf(m, fmaxf(fmaxf(fabsf(b.z), fabsf(b.w)), fabsf(c.x)));
    }
#pragma unroll
    for (int o = 16; o > 0; o >>= 1)
        m = fmaxf(m, __shfl_xor_sync(0xFFFFFFFFu, m, o));

    __shared__ float sm[T1 / 32];
    if ((tid & 31) == 0) sm[tid >> 5] = m;
    __syncthreads();
    if (tid == 0) {
        float mm = sm[0];
#pragma unroll
        for (int i = 1; i < T1 / 32; i++) mm = fmaxf(mm, sm[i]);
        // positive floats: uint compare == float compare
        atomicMax(&g_bbox[batch], __float_as_uint(mm));
    }
}

// ---------------------------------------------------------------------------
// Kernel 2: bin points, accumulate (count, sum_pic, sum_cov) per cell.
// Per-lane replica with bank-exact layout:
//   word addr = (cell*10 + s)*32 + lane   ->  bank == lane, always.
// Shared-memory atomics are therefore conflict-free by construction;
// atomics only arbitrate cross-warp same-lane collisions (rare, timing-random).
// ---------------------------------------------------------------------------
__device__ __forceinline__ void accum_point(
    float* __restrict__ h,   // hist + lane
    float px, float py, float pz,
    float ox, float oy, float oz,
    float bbox, float inv)
{
    float picx = (px + bbox) * inv;
    float picy = (py + bbox) * inv;
    float picz = (pz + bbox) * inv;
    int ix = (int)(picx * 4.0f); ix = min(max(ix, 0), 3);
    int iy = (int)(picy * 4.0f); iy = min(max(iy, 0), 3);
    int iz = (int)(picz * 4.0f); iz = min(max(iz, 0), 3);
    int cell = (ix * NUM_BINS + iy) * NUM_BINS + iz;
    float* d = h + cell * (STATS * REPL);
    atomicAdd(d + 0 * REPL, 1.0f);
    atomicAdd(d + 1 * REPL, picx);
    atomicAdd(d + 2 * REPL, picy);
    atomicAdd(d + 3 * REPL, picz);
    atomicAdd(d + 4 * REPL, ox * ox);
    atomicAdd(d + 5 * REPL, ox * oy);
    atomicAdd(d + 6 * REPL, ox * oz);
    atomicAdd(d + 7 * REPL, oy * oy);
    atomicAdd(d + 8 * REPL, oy * oz);
    atomicAdd(d + 9 * REPL, oz * oz);
}

extern __shared__ float hist[];   // HIST_WORDS floats (80 KB dynamic)

__global__ __launch_bounds__(T2) void k_accum(const float4* __restrict__ in4) {
    const int batch = blockIdx.y;
    const int tid = threadIdx.x;
    const int lane = tid & 31;

    // zero histogram (16B vector stores)
    float4* h4 = (float4*)hist;
#pragma unroll
    for (int i = tid; i < HIST_WORDS / 4; i += T2)
        h4[i] = make_float4(0.f, 0.f, 0.f, 0.f);
    __syncthreads();

    const float bbox = __uint_as_float(g_bbox[batch]);
    const float th = fmaxf(2.0f * bbox, 1e-5f);
    const float inv = 1.0f / th;

    const float4* p = in4 + (size_t)batch * F4_PER_B;
    const int base = blockIdx.x * PAIRS_PER_BLK2;
    float* hrep = hist + lane;

#pragma unroll 2
    for (int k = 0; k < ITER2; k++) {
        int j = base + tid + k * T2;
        float4 a = p[3 * j + 0];
        float4 b = p[3 * j + 1];
        float4 c = p[3 * j + 2];
        accum_point(hrep, a.x, a.y, a.z, a.w, b.x, b.y, bbox, inv);
        accum_point(hrep, b.z, b.w, c.x, c.y, c.z, c.w, bbox, inv);
    }
    __syncthreads();

    // Reduce 32 replicas per feature; rotate replica order by lane so the
    // 32 lanes of a warp read 32 distinct banks each step.
    for (int w = tid; w < FEAT; w += T2) {
        float s = 0.0f;
#pragma unroll
        for (int r = 0; r < REPL; r++)
            s += hist[w * REPL + ((r + lane) & 31)];
        atomicAdd(&g_sums[batch * FEAT + w], s);
    }
}

// ---------------------------------------------------------------------------
// Kernel 3: finalize. One block per batch, 640 threads = one (cell, stat).
//   f_freq    = 0.001 * n * rsqrt(max(n,1))
//   f_mean[d] = (sum_pic[d] - n * grid[d]) * rsqrt(max(n,1))
//   f_cov     = sum_cov / max(n,1)
// then L2-normalize the 640-vector. Afterwards restore g_sums/g_bbox to zero
// so the next replay starts from identical state.
// ---------------------------------------------------------------------------
__global__ __launch_bounds__(FEAT) void k_final(float* __restrict__ out) {
    const int b = blockIdx.x;
    const int t = threadIdx.x;               // 0..639
    const int cell = t / STATS;
    const int s = t - cell * STATS;

    float* sums = g_sums + b * FEAT;
    float cnt = sums[cell * STATS];
    float val = sums[t];
    float fc = fmaxf(cnt, 1.0f);
    float up = rsqrtf(fc);

    float f;
    if (s == 0) {
        f = 0.001f * cnt * up;
    } else if (s < 4) {
        int d = s - 1;
        int ci = (d == 0) ? (cell >> 4) : (d == 1) ? ((cell >> 2) & 3) : (cell & 3);
        float g = ((float)ci + 0.5f) * 0.25f;
        f = (val - cnt * g) * up;
    } else {
        f = val / fc;
    }

    // block-wide sum of f^2 over 640 threads (20 warps)
    float q = f * f;
#pragma unroll
    for (int o = 16; o > 0; o >>= 1)
        q += __shfl_xor_sync(0xFFFFFFFFu, q, o);

    __shared__ float wsum[FEAT / 32];
    __shared__ float s_inv;
    if ((t & 31) == 0) wsum[t >> 5] = q;
    __syncthreads();

    // all reads of g_sums are done -> restore zeros for next replay
    sums[t] = 0.0f;
    if (t == 0) {
        g_bbox[b] = 0u;
        float ss = 0.0f;
#pragma unroll
        for (int i = 0; i < FEAT / 32; i++) ss += wsum[i];
        float n = sqrtf(ss);
        s_inv = 1.0f / fmaxf(n, 1e-12f);
    }
    __syncthreads();

    out[b * FEAT + t] = f * s_inv;
}

// ---------------------------------------------------------------------------
extern "C" void kernel_launch(void* const* d_in, const int* in_sizes, int n_in,
                              void* d_out, int out_size) {
    const float4* in4 = (const float4*)d_in[0];
    float* out = (float*)d_out;
    (void)in_sizes; (void)n_in; (void)out_size;

    cudaFuncSetAttribute(k_accum, cudaFuncAttributeMaxDynamicSharedMemorySize,
                         HIST_BYTES);

    k_bbox<<<dim3(BPB1, BATCHES), T1>>>(in4);
    k_accum<<<dim3(BPB2, BATCHES), T2, HIST_BYTES>>>(in4);
    k_final<<<BATCHES, FEAT>>>(out);
}